// round 10
// baseline (speedup 1.0000x reference)
#include <cuda_runtime.h>

// DeepArcNet v6: tf32 mma.sync tensor-core GEMMs.
// Block = 16 samples = 96 columns. Activations [72][104] f32 in shared
// (stride 104 -> conflict-free B-fragments), weights staged tf32-rounded
// [68][76]. 6 warps each own an m16 x n-range tile; softmax/LN/conv scalar.

#define TPB 192
#define SPB 16

typedef unsigned int uint32;
typedef unsigned long long ull;

// float offsets in dynamic shared (110,800 B)
#define WT_F  0                     // [68][76] weights (tf32 bits) / fc floats
#define H_F   5168                  // [72][104]
#define A_F   (H_F + 7488)
#define B_F   (A_F + 7488)
#define POS_F (B_F + 7488)          // [68]
#define RED_F 2448                  // aliases WT tail during fc
#define SM_FLOATS (POS_F + 68)      // 27700

#define AST 104                     // activation row stride
#define WST 76                      // weight row stride

__device__ __forceinline__ float tf32r(float f) {
  uint32 u; asm("cvt.rna.tf32.f32 %0, %1;" : "=r"(u) : "f"(f));
  return __uint_as_float(u);
}
__device__ __forceinline__ uint32 fbits(float f) { return __float_as_uint(f); }

__device__ __forceinline__ void mma8(float* c, const uint32* a, const uint32* b) {
  asm volatile(
    "mma.sync.aligned.m16n8k8.row.col.f32.tf32.tf32.f32 "
    "{%0,%1,%2,%3},{%4,%5,%6,%7},{%8,%9},{%0,%1,%2,%3};"
    : "+f"(c[0]), "+f"(c[1]), "+f"(c[2]), "+f"(c[3])
    : "r"(a[0]), "r"(a[1]), "r"(a[2]), "r"(a[3]), "r"(b[0]), "r"(b[1]));
}

// stage W[NR][K] (row-major) -> wt[68][76] tf32-rounded, zero beyond NR/K
__device__ __forceinline__ void stage_w(float* wt, const float* __restrict__ src,
                                        int NR, int K, int tid) {
#pragma unroll 1
  for (int idx = tid; idx < 68 * WST; idx += TPB) {
    int d = idx / WST, e = idx - d * WST;
    float v = (d < NR && e < K) ? tf32r(__ldg(src + d * K + e)) : 0.f;
    wt[idx] = v;
  }
}

// warp-level gemm: dst[NR][96] = W * src (+bias, opt relu, opt tf32-round)
// KT k-tiles of 8. Warp tile config derived from NR and wid.
__device__ __forceinline__ void gemm_mma(const float* wt, const float* src,
                                         float* dst, int NR, int KT,
                                         const float* __restrict__ bias,
                                         bool relu, bool rnd, int wid, int lane) {
  int gid = lane >> 2, tig = lane & 3;
  int mt, n0, n1;
  if (NR > 34) {            // 68 rows -> 5 m-tiles; warps 4,5 split m-tile 4
    if (wid < 4) { mt = wid; n0 = 0; n1 = 12; }
    else         { mt = 4; n0 = (wid - 4) * 6; n1 = n0 + 6; }
  } else {                  // 34 rows -> 3 m-tiles x 2 n-halves
    mt = wid >> 1; n0 = (wid & 1) * 6; n1 = n0 + 6;
  }
  float acc[48];
#pragma unroll
  for (int i = 0; i < 48; i++) acc[i] = 0.f;

#pragma unroll 1
  for (int kt = 0; kt < KT; kt++) {
    const float* ap = wt + (mt * 16 + gid) * WST + kt * 8 + tig;
    uint32 a[4];
    a[0] = fbits(ap[0]);
    a[1] = fbits(ap[8 * WST]);
    a[2] = fbits(ap[4]);
    a[3] = fbits(ap[8 * WST + 4]);
    const float* bp0 = src + (kt * 8 + tig) * AST + gid;
#pragma unroll
    for (int nt = 0; nt < 12; nt++) {
      if (nt < n1 - n0) {
        const float* bp = bp0 + (n0 + nt) * 8;
        uint32 b[2];
        b[0] = fbits(bp[0]);
        b[1] = fbits(bp[4 * AST]);
        mma8(acc + nt * 4, a, b);
      }
    }
  }

  int r0 = mt * 16 + gid, r1 = r0 + 8;
  float bz0 = (bias && r0 < NR) ? __ldg(bias + r0) : 0.f;
  float bz1 = (bias && r1 < NR) ? __ldg(bias + r1) : 0.f;
#pragma unroll
  for (int nt = 0; nt < 12; nt++) {
    if (nt < n1 - n0) {
      int col = (n0 + nt) * 8 + 2 * tig;
      float v0 = acc[nt * 4 + 0] + bz0, v1 = acc[nt * 4 + 1] + bz0;
      float v2 = acc[nt * 4 + 2] + bz1, v3 = acc[nt * 4 + 3] + bz1;
      if (relu) { v0 = fmaxf(v0, 0.f); v1 = fmaxf(v1, 0.f);
                  v2 = fmaxf(v2, 0.f); v3 = fmaxf(v3, 0.f); }
      if (rnd) { v0 = tf32r(v0); v1 = tf32r(v1); v2 = tf32r(v2); v3 = tf32r(v3); }
      if (r0 < NR) { dst[r0 * AST + col] = v0; dst[r0 * AST + col + 1] = v1; }
      if (r1 < NR) { dst[r1 * AST + col] = v2; dst[r1 * AST + col + 1] = v3; }
    }
  }
}

__global__ void __launch_bounds__(TPB) dan_kernel(
    const float* __restrict__ x,     const float* __restrict__ convw,
    const float* __restrict__ convb, const float* __restrict__ lembw,
    const float* __restrict__ lembb, const float* __restrict__ wq,
    const float* __restrict__ wk,    const float* __restrict__ wv,
    const float* __restrict__ projw, const float* __restrict__ projb,
    const float* __restrict__ ff1w,  const float* __restrict__ ff1b,
    const float* __restrict__ ff2w,  const float* __restrict__ ff2b,
    const float* __restrict__ ln1g,  const float* __restrict__ ln1b,
    const float* __restrict__ ln2g,  const float* __restrict__ ln2b,
    const float* __restrict__ lnfg,  const float* __restrict__ lnfb,
    const float* __restrict__ fcw,   const float* __restrict__ fcb,
    float* __restrict__ out)
{
  extern __shared__ float smf[];
  float* Wt = smf + WT_F;
  float* Hs = smf + H_F;
  float* As = smf + A_F;
  float* Bs = smf + B_F;
  const int tid = threadIdx.x;
  const int wid = tid >> 5, lane = tid & 31;
  const int samp0 = blockIdx.x * SPB;
  const int g = tid / 96, c = tid - g * 96;   // head-group, column
  const int s = c / 6, t = c - s * 6;

  // pos table (into POS region)
  if (tid < 68) {
    int tt = tid >> 2, j4 = tid & 3;
    float ang = (j4 & 1) ? ((float)tt * (1.0f / 18.0f)) : (float)tt;
    smf[POS_F + tid] = (j4 < 2) ? sinf(ang) : cosf(ang);
  }

  // depthwise conv -> scratch (A region, rows 0..)
#pragma unroll 1
  for (int o = tid; o < SPB * 102; o += TPB) {
    int ss = o / 102, r = o % 102, ch = r / 17, tt = r % 17;
    const float* xp = x + ((size_t)(samp0 + ss) * 6 + ch) * 185 + tt * 10;
    float acc = 0.f;
#pragma unroll
    for (int i = 0; i < 25; i++) acc = fmaf(__ldg(xp + i), __ldg(convw + ch * 25 + i), acc);
    As[ss * 102 + ch * 17 + tt] = fmaxf(acc + __ldg(convb + ch), 0.f);
  }
  __syncthreads();

  // embed -> H (tf32-rounded); zero pad rows of H, B
  if (tid < 96) {
    float lw[4], lb[4];
#pragma unroll
    for (int q4 = 0; q4 < 4; q4++) {
      lw[q4] = __ldg(lembw + t * 4 + q4);
      lb[q4] = __ldg(lembb + t * 4 + q4);
    }
#pragma unroll 1
    for (int tt = 0; tt < 17; tt++) {
      float xv = As[s * 102 + t * 17 + tt];
#pragma unroll
      for (int q4 = 0; q4 < 4; q4++) {
        int e = tt * 4 + q4;
        Hs[e * AST + c] = tf32r(fmaf(xv, lw[q4], lb[q4]) + smf[POS_F + e]);
      }
    }
  }
#pragma unroll 1
  for (int idx = tid; idx < 4 * AST; idx += TPB) {
    Hs[68 * AST + idx] = 0.f;
    Bs[68 * AST + idx] = 0.f;
  }
  __syncthreads();

  float p[6];  // softmax probs

#pragma unroll 1
  for (int l = 0; l < 2; l++) {
    // Q
    stage_w(Wt, wq + l * 4624, 68, 68, tid);
    __syncthreads();
    gemm_mma(Wt, Hs, As, 68, 9, nullptr, false, false, wid, lane);
    __syncthreads();
    // K
    stage_w(Wt, wk + l * 4624, 68, 68, tid);
    __syncthreads();
    gemm_mma(Wt, Hs, Bs, 68, 9, nullptr, false, false, wid, lane);
    __syncthreads();
    // zero A pad rows (A now = Q; pad rows needed zero before V-gemm writes..A reused)
    // softmax (A=Q, B=K); then stage Wv
    {
      float qv[34];
#pragma unroll 1
      for (int d = 0; d < 34; d++) qv[d] = As[(g * 34 + d) * AST + c];
      float sc[6];
#pragma unroll 1
      for (int t2 = 0; t2 < 6; t2++) {
        float a2 = 0.f;
#pragma unroll
        for (int d = 0; d < 34; d++)
          a2 = fmaf(qv[d], Bs[(g * 34 + d) * AST + s * 6 + t2], a2);
        sc[t2] = a2 * 0.17149858514f;  // 34^-0.5
      }
      float mx = sc[0];
#pragma unroll
      for (int t2 = 1; t2 < 6; t2++) mx = fmaxf(mx, sc[t2]);
      float ssum = 0.f;
#pragma unroll
      for (int t2 = 0; t2 < 6; t2++) { sc[t2] = __expf(sc[t2] - mx); ssum += sc[t2]; }
      float inv = 1.0f / ssum;
#pragma unroll
      for (int t2 = 0; t2 < 6; t2++) p[t2] = sc[t2] * inv;
    }
    stage_w(Wt, wv + l * 4624, 68, 68, tid);
    __syncthreads();
    // V -> A (Q consumed)
    gemm_mma(Wt, Hs, As, 68, 9, nullptr, false, false, wid, lane);
    __syncthreads();
    // attn = p*V -> B (tf32-rounded; feeds proj gemm); stage proj
#pragma unroll 1
    for (int dd = 0; dd < 34; dd++) {
      float a2 = 0.f;
#pragma unroll
      for (int t2 = 0; t2 < 6; t2++)
        a2 = fmaf(p[t2], As[(g * 34 + dd) * AST + s * 6 + t2], a2);
      Bs[(g * 34 + dd) * AST + c] = tf32r(a2);
    }
    stage_w(Wt, projw + l * 4624, 68, 68, tid);
    __syncthreads();
    // proj(B) -> A (+bias)
    gemm_mma(Wt, Bs, As, 68, 9, projb + l * 68, false, false, wid, lane);
    __syncthreads();
    // LN1: H = LN(H + A), rounded; stage ff1
    if (tid < 96) {
      float h[68]; float m = 0.f;
#pragma unroll
      for (int e = 0; e < 68; e++) { h[e] = Hs[e * AST + c] + As[e * AST + c]; m += h[e]; }
      m *= (1.0f / 68.0f);
      float v = 0.f;
#pragma unroll
      for (int e = 0; e < 68; e++) { float d = h[e] - m; v = fmaf(d, d, v); }
      float rr = rsqrtf(v * (1.0f / 68.0f) + 1e-5f);
#pragma unroll
      for (int e = 0; e < 68; e++)
        Hs[e * AST + c] = tf32r(fmaf((h[e] - m) * rr, __ldg(ln1g + l * 68 + e),
                                     __ldg(ln1b + l * 68 + e)));
    }
    stage_w(Wt, ff1w + l * 2312, 34, 68, tid);
    __syncthreads();
    // ff1(H) -> A rows 0..33 (+bias, relu, rounded: feeds ff2 gemm)
    gemm_mma(Wt, Hs, As, 34, 9, ff1b + l * 34, true, true, wid, lane);
    __syncthreads();
    // zero A rows 34..39 (k-pad for ff2); stage ff2 (K=34 -> cols 34+ zeroed)
#pragma unroll 1
    for (int idx = tid; idx < 6 * AST; idx += TPB) As[34 * AST + idx] = 0.f;
    stage_w(Wt, ff2w + l * 2312, 68, 34, tid);
    __syncthreads();
    // ff2(A) -> B (+bias)
    gemm_mma(Wt, As, Bs, 68, 5, ff2b + l * 68, false, false, wid, lane);
    __syncthreads();
    // LN2 (+final LN): H = LN(H + B), rounded
    if (tid < 96) {
      float h[68]; float m = 0.f;
#pragma unroll
      for (int e = 0; e < 68; e++) { h[e] = Hs[e * AST + c] + Bs[e * AST + c]; m += h[e]; }
      m *= (1.0f / 68.0f);
      float v = 0.f;
#pragma unroll
      for (int e = 0; e < 68; e++) { float d = h[e] - m; v = fmaf(d, d, v); }
      float rr = rsqrtf(v * (1.0f / 68.0f) + 1e-5f);
#pragma unroll
      for (int e = 0; e < 68; e++)
        h[e] = fmaf((h[e] - m) * rr, __ldg(ln2g + l * 68 + e), __ldg(ln2b + l * 68 + e));
      if (l == 1) {
        m = 0.f;
#pragma unroll
        for (int e = 0; e < 68; e++) m += h[e];
        m *= (1.0f / 68.0f);
        v = 0.f;
#pragma unroll
        for (int e = 0; e < 68; e++) { float d = h[e] - m; v = fmaf(d, d, v); }
        rr = rsqrtf(v * (1.0f / 68.0f) + 1e-5f);
#pragma unroll
        for (int e = 0; e < 68; e++)
          h[e] = fmaf((h[e] - m) * rr, __ldg(lnfg + e), __ldg(lnfb + e));
      }
#pragma unroll
      for (int e = 0; e < 68; e++) Hs[e * AST + c] = h[e];
    }
    __syncthreads();
  }

  // final FC: stage fcw floats into WT, per-column dots, reduce
#pragma unroll 1
  for (int idx = tid; idx < 2448; idx += TPB) Wt[idx] = __ldg(fcw + idx);
  __syncthreads();
  if (tid < 96) {
    float h[68];
#pragma unroll
    for (int e = 0; e < 68; e++) h[e] = Hs[e * AST + c];
#pragma unroll 1
    for (int o = 0; o < 6; o++) {
      const float* wrow = Wt + o * 408 + t * 68;
      float a2 = 0.f;
#pragma unroll
      for (int e = 0; e < 68; e++) a2 = fmaf(h[e], wrow[e], a2);
      smf[RED_F + s * 36 + t * 6 + o] = a2;
    }
  }
  __syncthreads();
  if (tid < SPB) {
    int ss = tid;
#pragma unroll 1
    for (int o = 0; o < 6; o++) {
      float v = __ldg(fcb + o);
#pragma unroll
      for (int tt = 0; tt < 6; tt++) v += smf[RED_F + ss * 36 + tt * 6 + o];
      out[(size_t)(samp0 + ss) * 6 + o] = fmaxf(v, 0.f);
    }
  }
}

extern "C" void kernel_launch(void* const* d_in, const int* in_sizes, int n_in,
                              void* d_out, int out_size) {
  const float* x     = (const float*)d_in[0];
  const float* convw = (const float*)d_in[1];
  const float* convb = (const float*)d_in[2];
  const float* lembw = (const float*)d_in[3];
  const float* lembb = (const float*)d_in[4];
  const float* wq    = (const float*)d_in[5];
  const float* wk    = (const float*)d_in[6];
  const float* wv    = (const float*)d_in[7];
  const float* projw = (const float*)d_in[8];
  const float* projb = (const float*)d_in[9];
  const float* ff1w  = (const float*)d_in[10];
  const float* ff1b  = (const float*)d_in[11];
  const float* ff2w  = (const float*)d_in[12];
  const float* ff2b  = (const float*)d_in[13];
  const float* ln1g  = (const float*)d_in[14];
  const float* ln1b  = (const float*)d_in[15];
  const float* ln2g  = (const float*)d_in[16];
  const float* ln2b  = (const float*)d_in[17];
  const float* lnfg  = (const float*)d_in[18];
  const float* lnfb  = (const float*)d_in[19];
  const float* fcw   = (const float*)d_in[20];
  const float* fcb   = (const float*)d_in[21];
  float* out = (float*)d_out;

  int B = in_sizes[0] / (6 * 37 * 5);   // 32768
  int grid = B / SPB;                   // 2048
  int smem = SM_FLOATS * 4;             // 110,800 B

  static int configured = 0;
  if (!configured) {
    cudaFuncSetAttribute(dan_kernel, cudaFuncAttributeMaxDynamicSharedMemorySize, smem);
    configured = 1;
  }
  dan_kernel<<<grid, TPB, smem>>>(
      x, convw, convb, lembw, lembb, wq, wk, wv, projw, projb,
      ff1w, ff1b, ff2w, ff2b, ln1g, ln1b, ln2g, ln2b, lnfg, lnfb,
      fcw, fcb, out);
}

// round 11
// speedup vs baseline: 1.7439x; 1.7439x over previous
#include <cuda_runtime.h>

// DeepArcNet v7: tf32 mma.sync GEMMs with PRE-COMPUTED fragment-major weights.
// A prep kernel writes, once per launch, all 12 gemm weight matrices as
// per-(mtile,ktile,lane) mma fragments (tf32, zero-padded) into a __device__
// global. The main kernel's A-operand load is then ONE coalesced LDG.128 per
// k-tile (L1-resident) -- no weight smem, no staging phases, no staging ALU.

#define TPB 192
#define SPB 16
#define AST 104                      // activation row stride (8 mod 32 -> conflict-free B frags)

typedef unsigned int uint32;

// 12 slots x 5 mtiles x 9 ktiles x 32 lanes x 4 regs
__device__ float g_wfrag[12 * 5 * 9 * 128];

// float offsets in dynamic shared (90,128 B)
#define H_F   0                      // [72][104]
#define A_F   7488                   // (aliased: conv scratch, fc weights)
#define B_F   (2 * 7488)             // (aliased: fc reduce)
#define POS_F (3 * 7488)             // [68]
#define SM_FLOATS (POS_F + 68)

__device__ __forceinline__ float tf32r(float f) {
  uint32 u; asm("cvt.rna.tf32.f32 %0, %1;" : "=r"(u) : "f"(f));
  return __uint_as_float(u);
}
__device__ __forceinline__ uint32 fbits(float f) { return __float_as_uint(f); }

__device__ __forceinline__ void mma8(float* c, const uint32* a, const uint32* b) {
  asm volatile(
    "mma.sync.aligned.m16n8k8.row.col.f32.tf32.tf32.f32 "
    "{%0,%1,%2,%3},{%4,%5,%6,%7},{%8,%9},{%0,%1,%2,%3};"
    : "+f"(c[0]), "+f"(c[1]), "+f"(c[2]), "+f"(c[3])
    : "r"(a[0]), "r"(a[1]), "r"(a[2]), "r"(a[3]), "r"(b[0]), "r"(b[1]));
}

// ---- prep kernel: build fragment-major tf32 weights ----
__global__ void prep_kernel(const float* __restrict__ wq, const float* __restrict__ wk,
                            const float* __restrict__ wv, const float* __restrict__ projw,
                            const float* __restrict__ ff1w, const float* __restrict__ ff2w) {
  int idx = blockIdx.x * blockDim.x + threadIdx.x;
  if (idx >= 12 * 5 * 9 * 32) return;
  int lane = idx & 31;
  int kt = (idx >> 5) % 9;
  int mt = (idx / 288) % 5;
  int slot = idx / 1440;
  int l = slot / 6, w = slot % 6;
  const float* src; int NR, K;
  switch (w) {
    case 0:  src = wq + l * 4624;    NR = 68; K = 68; break;
    case 1:  src = wk + l * 4624;    NR = 68; K = 68; break;
    case 2:  src = wv + l * 4624;    NR = 68; K = 68; break;
    case 3:  src = projw + l * 4624; NR = 68; K = 68; break;
    case 4:  src = ff1w + l * 2312;  NR = 34; K = 68; break;
    default: src = ff2w + l * 2312;  NR = 68; K = 34; break;
  }
  int gid = lane >> 2, tig = lane & 3;
  int r0 = mt * 16 + gid, r1 = r0 + 8;
  int k0 = kt * 8 + tig, k1 = k0 + 4;
  float4 v;
  v.x = (r0 < NR && k0 < K) ? tf32r(__ldg(src + r0 * K + k0)) : 0.f;
  v.y = (r1 < NR && k0 < K) ? tf32r(__ldg(src + r1 * K + k0)) : 0.f;
  v.z = (r0 < NR && k1 < K) ? tf32r(__ldg(src + r0 * K + k1)) : 0.f;
  v.w = (r1 < NR && k1 < K) ? tf32r(__ldg(src + r1 * K + k1)) : 0.f;
  reinterpret_cast<float4*>(g_wfrag)[idx] = v;
}

// ---- warp gemm: dst[NR][96] = W(slot) * src  (+bias, opt relu, opt tf32 round) ----
__device__ __forceinline__ void gemm_mma(int slot, const float* src, float* dst,
                                         int NR, int KT, const float* __restrict__ bias,
                                         bool relu, bool rnd, int wid, int lane) {
  int gid = lane >> 2, tig = lane & 3;
  int mt, n0, nN;
  if (NR > 34) {
    if (wid < 4) { mt = wid; n0 = 0; nN = 12; }
    else         { mt = 4; n0 = (wid - 4) * 6; nN = 6; }
  } else {
    mt = wid >> 1; n0 = (wid & 1) * 6; nN = 6;
  }
  float acc[48];
#pragma unroll
  for (int i = 0; i < 48; i++) acc[i] = 0.f;

  const float4* afrag = reinterpret_cast<const float4*>(g_wfrag)
                        + (slot * 5 + mt) * 9 * 32 + lane;
#pragma unroll 1
  for (int kt = 0; kt < KT; kt++) {
    float4 av = afrag[kt * 32];            // one coalesced LDG.128 / warp / ktile
    uint32 a[4] = { fbits(av.x), fbits(av.y), fbits(av.z), fbits(av.w) };
    const float* bp0 = src + (kt * 8 + tig) * AST + gid;
#pragma unroll
    for (int nt = 0; nt < 12; nt++) {
      if (nt < nN) {
        const float* bp = bp0 + (n0 + nt) * 8;
        uint32 b[2] = { fbits(bp[0]), fbits(bp[4 * AST]) };
        mma8(acc + nt * 4, a, b);
      }
    }
  }

  int r0 = mt * 16 + gid, r1 = r0 + 8;
  float bz0 = (bias && r0 < NR) ? __ldg(bias + r0) : 0.f;
  float bz1 = (bias && r1 < NR) ? __ldg(bias + r1) : 0.f;
#pragma unroll
  for (int nt = 0; nt < 12; nt++) {
    if (nt < nN) {
      int col = (n0 + nt) * 8 + 2 * tig;
      float v0 = acc[nt * 4 + 0] + bz0, v1 = acc[nt * 4 + 1] + bz0;
      float v2 = acc[nt * 4 + 2] + bz1, v3 = acc[nt * 4 + 3] + bz1;
      if (relu) { v0 = fmaxf(v0, 0.f); v1 = fmaxf(v1, 0.f);
                  v2 = fmaxf(v2, 0.f); v3 = fmaxf(v3, 0.f); }
      if (rnd) { v0 = tf32r(v0); v1 = tf32r(v1); v2 = tf32r(v2); v3 = tf32r(v3); }
      if (r0 < NR) { dst[r0 * AST + col] = v0; dst[r0 * AST + col + 1] = v1; }
      if (r1 < NR) { dst[r1 * AST + col] = v2; dst[r1 * AST + col + 1] = v3; }
    }
  }
}

__global__ void __launch_bounds__(TPB) dan_kernel(
    const float* __restrict__ x,     const float* __restrict__ convw,
    const float* __restrict__ convb, const float* __restrict__ lembw,
    const float* __restrict__ lembb, const float* __restrict__ projb,
    const float* __restrict__ ff1b,  const float* __restrict__ ff2b,
    const float* __restrict__ ln1g,  const float* __restrict__ ln1b,
    const float* __restrict__ ln2g,  const float* __restrict__ ln2b,
    const float* __restrict__ lnfg,  const float* __restrict__ lnfb,
    const float* __restrict__ fcw,   const float* __restrict__ fcb,
    float* __restrict__ out)
{
  extern __shared__ float smf[];
  float* Hs = smf + H_F;
  float* As = smf + A_F;
  float* Bs = smf + B_F;
  const int tid = threadIdx.x;
  const int wid = tid >> 5, lane = tid & 31;
  const int samp0 = blockIdx.x * SPB;
  const int g = tid / 96, c = tid - g * 96;   // head-group, column
  const int s = c / 6, t = c - s * 6;

  // pos table
  if (tid < 68) {
    int tt = tid >> 2, j4 = tid & 3;
    float ang = (j4 & 1) ? ((float)tt * (1.0f / 18.0f)) : (float)tt;
    smf[POS_F + tid] = (j4 < 2) ? sinf(ang) : cosf(ang);
  }

  // depthwise conv 5x5 stride(2,2) -> scratch in A
#pragma unroll 1
  for (int o = tid; o < SPB * 102; o += TPB) {
    int ss = o / 102, r = o % 102, ch = r / 17, tt = r % 17;
    const float* xp = x + ((size_t)(samp0 + ss) * 6 + ch) * 185 + tt * 10;
    float acc = 0.f;
#pragma unroll
    for (int i = 0; i < 25; i++) acc = fmaf(__ldg(xp + i), __ldg(convw + ch * 25 + i), acc);
    As[ss * 102 + ch * 17 + tt] = fmaxf(acc + __ldg(convb + ch), 0.f);
  }
  __syncthreads();

  // embed -> H (tf32-rounded); zero pad rows 68..71 of H and B
  if (tid < 96) {
    float lw[4], lb[4];
#pragma unroll
    for (int q4 = 0; q4 < 4; q4++) {
      lw[q4] = __ldg(lembw + t * 4 + q4);
      lb[q4] = __ldg(lembb + t * 4 + q4);
    }
#pragma unroll 1
    for (int tt = 0; tt < 17; tt++) {
      float xv = As[s * 102 + t * 17 + tt];
#pragma unroll
      for (int q4 = 0; q4 < 4; q4++) {
        int e = tt * 4 + q4;
        Hs[e * AST + c] = tf32r(fmaf(xv, lw[q4], lb[q4]) + smf[POS_F + e]);
      }
    }
  }
#pragma unroll 1
  for (int idx = tid; idx < 4 * AST; idx += TPB) {
    Hs[68 * AST + idx] = 0.f;
    Bs[68 * AST + idx] = 0.f;
  }
  __syncthreads();

  float p[6];  // softmax probs

#pragma unroll 1
  for (int l = 0; l < 2; l++) {
    int sl = l * 6;
    // Q -> A, K -> B (both read only H; disjoint outputs; one phase)
    gemm_mma(sl + 0, Hs, As, 68, 9, nullptr, false, false, wid, lane);
    gemm_mma(sl + 1, Hs, Bs, 68, 9, nullptr, false, false, wid, lane);
    __syncthreads();
    // softmax (A=Q, B=K -> p)
    {
      float qv[34];
#pragma unroll 1
      for (int d = 0; d < 34; d++) qv[d] = As[(g * 34 + d) * AST + c];
      float sc[6];
#pragma unroll 1
      for (int t2 = 0; t2 < 6; t2++) {
        float a2 = 0.f;
#pragma unroll
        for (int d = 0; d < 34; d++)
          a2 = fmaf(qv[d], Bs[(g * 34 + d) * AST + s * 6 + t2], a2);
        sc[t2] = a2 * 0.17149858514f;  // 34^-0.5
      }
      float mx = sc[0];
#pragma unroll
      for (int t2 = 1; t2 < 6; t2++) mx = fmaxf(mx, sc[t2]);
      float ssum = 0.f;
#pragma unroll
      for (int t2 = 0; t2 < 6; t2++) { sc[t2] = __expf(sc[t2] - mx); ssum += sc[t2]; }
      float inv = 1.0f / ssum;
#pragma unroll
      for (int t2 = 0; t2 < 6; t2++) p[t2] = sc[t2] * inv;
    }
    __syncthreads();
    // V -> A (Q consumed)
    gemm_mma(sl + 2, Hs, As, 68, 9, nullptr, false, false, wid, lane);
    __syncthreads();
    // attn = p*V -> B (tf32-rounded; feeds proj gemm)
#pragma unroll 1
    for (int dd = 0; dd < 34; dd++) {
      float a2 = 0.f;
#pragma unroll
      for (int t2 = 0; t2 < 6; t2++)
        a2 = fmaf(p[t2], As[(g * 34 + dd) * AST + s * 6 + t2], a2);
      Bs[(g * 34 + dd) * AST + c] = tf32r(a2);
    }
    __syncthreads();
    // proj(B) -> A (+bias)
    gemm_mma(sl + 3, Bs, As, 68, 9, projb + l * 68, false, false, wid, lane);
    __syncthreads();
    // LN1: H = LN(H + A), rounded
    if (tid < 96) {
      float h[68]; float m = 0.f;
#pragma unroll
      for (int e = 0; e < 68; e++) { h[e] = Hs[e * AST + c] + As[e * AST + c]; m += h[e]; }
      m *= (1.0f / 68.0f);
      float v = 0.f;
#pragma unroll
      for (int e = 0; e < 68; e++) { float d = h[e] - m; v = fmaf(d, d, v); }
      float rr = rsqrtf(v * (1.0f / 68.0f) + 1e-5f);
#pragma unroll
      for (int e = 0; e < 68; e++)
        Hs[e * AST + c] = tf32r(fmaf((h[e] - m) * rr, __ldg(ln1g + l * 68 + e),
                                     __ldg(ln1b + l * 68 + e)));
    }
    __syncthreads();
    // ff1(H) -> A rows 0..33 (+bias, relu, rounded); zero A rows 34..39 (k-pad)
    gemm_mma(sl + 4, Hs, As, 34, 9, ff1b + l * 34, true, true, wid, lane);
#pragma unroll 1
    for (int idx = tid; idx < 6 * AST; idx += TPB) As[34 * AST + idx] = 0.f;
    __syncthreads();
    // ff2(A) -> B (+bias)
    gemm_mma(sl + 5, As, Bs, 68, 5, ff2b + l * 68, false, false, wid, lane);
    __syncthreads();
    // LN2 (+final LN): H = LN(H + B); stage fcw into A on last layer
    if (tid < 96) {
      float h[68]; float m = 0.f;
#pragma unroll
      for (int e = 0; e < 68; e++) { h[e] = Hs[e * AST + c] + Bs[e * AST + c]; m += h[e]; }
      m *= (1.0f / 68.0f);
      float v = 0.f;
#pragma unroll
      for (int e = 0; e < 68; e++) { float d = h[e] - m; v = fmaf(d, d, v); }
      float rr = rsqrtf(v * (1.0f / 68.0f) + 1e-5f);
#pragma unroll
      for (int e = 0; e < 68; e++)
        h[e] = fmaf((h[e] - m) * rr, __ldg(ln2g + l * 68 + e), __ldg(ln2b + l * 68 + e));
      if (l == 1) {
        m = 0.f;
#pragma unroll
        for (int e = 0; e < 68; e++) m += h[e];
        m *= (1.0f / 68.0f);
        v = 0.f;
#pragma unroll
        for (int e = 0; e < 68; e++) { float d = h[e] - m; v = fmaf(d, d, v); }
        rr = rsqrtf(v * (1.0f / 68.0f) + 1e-5f);
#pragma unroll
        for (int e = 0; e < 68; e++)
          h[e] = fmaf((h[e] - m) * rr, __ldg(lnfg + e), __ldg(lnfb + e));
      }
#pragma unroll
      for (int e = 0; e < 68; e++) Hs[e * AST + c] = h[e];
    }
    if (l == 1) {
#pragma unroll 1
      for (int idx = tid; idx < 2448; idx += TPB) As[idx] = __ldg(fcw + idx);
    }
    __syncthreads();
  }

  // final FC [6 x 408] (weights in A); partials -> B; reduce
  if (tid < 96) {
    float h[68];
#pragma unroll
    for (int e = 0; e < 68; e++) h[e] = Hs[e * AST + c];
#pragma unroll 1
    for (int o = 0; o < 6; o++) {
      const float* wrow = As + o * 408 + t * 68;
      float a2 = 0.f;
#pragma unroll
      for (int e = 0; e < 68; e++) a2 = fmaf(h[e], wrow[e], a2);
      Bs[s * 36 + t * 6 + o] = a2;
    }
  }
  __syncthreads();
  if (tid < SPB) {
    int ss = tid;
#pragma unroll 1
    for (int o = 0; o < 6; o++) {
      float v = __ldg(fcb + o);
#pragma unroll
      for (int tt = 0; tt < 6; tt++) v += Bs[ss * 36 + tt * 6 + o];
      out[(size_t)(samp0 + ss) * 6 + o] = fmaxf(v, 0.f);
    }
  }
}

extern "C" void kernel_launch(void* const* d_in, const int* in_sizes, int n_in,
                              void* d_out, int out_size) {
  const float* x     = (const float*)d_in[0];
  const float* convw = (const float*)d_in[1];
  const float* convb = (const float*)d_in[2];
  const float* lembw = (const float*)d_in[3];
  const float* lembb = (const float*)d_in[4];
  const float* wq    = (const float*)d_in[5];
  const float* wk    = (const float*)d_in[6];
  const float* wv    = (const float*)d_in[7];
  const float* projw = (const float*)d_in[8];
  const float* projb = (const float*)d_in[9];
  const float* ff1w  = (const float*)d_in[10];
  const float* ff1b  = (const float*)d_in[11];
  const float* ff2w  = (const float*)d_in[12];
  const float* ff2b  = (const float*)d_in[13];
  const float* ln1g  = (const float*)d_in[14];
  const float* ln1b  = (const float*)d_in[15];
  const float* ln2g  = (const float*)d_in[16];
  const float* ln2b  = (const float*)d_in[17];
  const float* lnfg  = (const float*)d_in[18];
  const float* lnfb  = (const float*)d_in[19];
  const float* fcw   = (const float*)d_in[20];
  const float* fcb   = (const float*)d_in[21];
  float* out = (float*)d_out;

  int B = in_sizes[0] / (6 * 37 * 5);   // 32768
  int grid = B / SPB;                   // 2048
  int smem = SM_FLOATS * 4;             // 90,128 B

  static int configured = 0;
  if (!configured) {
    cudaFuncSetAttribute(dan_kernel, cudaFuncAttributeMaxDynamicSharedMemorySize, smem);
    configured = 1;
  }
  prep_kernel<<<68, 256>>>(wq, wk, wv, projw, ff1w, ff2w);
  dan_kernel<<<grid, TPB, smem>>>(
      x, convw, convb, lembw, lembb, projb, ff1b, ff2b,
      ln1g, ln1b, ln2g, ln2b, lnfg, lnfb, fcw, fcb, out);
}